// round 3
// baseline (speedup 1.0000x reference)
#include <cuda_runtime.h>
#include <cuda_bf16.h>

// ---------------------------------------------------------------------------
// Classifier: out[e] = MLP(concat(x_drug[i_e], x_disease[j_e]))
// Layer-1 factored per-node:
//   h_drug    = x_drug    @ W1[0:100]   + b1     (n_drug x 128)
//   h_disease = x_disease @ W1[100:200]          (n_dis  x 128)
// per edge: h = leaky(h_drug[i] + h_disease[j]); then 128->32->16->1.
// ---------------------------------------------------------------------------

#define MAX_NODES 16384
__device__ float g_hd[MAX_NODES * 128];
__device__ float g_he[MAX_NODES * 128];
__device__ int   g_idx64;   // 1 if edge index buffer is int64, 0 if int32

__device__ __forceinline__ float lrelu(float v) {
    return v >= 0.0f ? v : 0.01f * v;
}

// packed f32x2 helpers (sm_103a; ptxas never auto-fuses these)
__device__ __forceinline__ unsigned long long pk2(float a, float b) {
    unsigned long long r;
    asm("mov.b64 %0, {%1, %2};" : "=l"(r) : "f"(a), "f"(b));
    return r;
}
__device__ __forceinline__ void up2(unsigned long long v, float& a, float& b) {
    asm("mov.b64 {%0, %1}, %2;" : "=f"(a), "=f"(b) : "l"(v));
}
__device__ __forceinline__ unsigned long long fma2(unsigned long long a,
                                                   unsigned long long b,
                                                   unsigned long long c) {
    unsigned long long d;
    asm("fma.rn.f32x2 %0, %1, %2, %3;" : "=l"(d) : "l"(a), "l"(b), "l"(c));
    return d;
}

__device__ __forceinline__ long long load_idx(const void* ell, long long pos,
                                              int is64) {
    if (is64) return ((const long long*)ell)[pos];
    return (long long)((const int*)ell)[pos];
}

// ---------------------------------------------------------------------------
// Kernel 1: tiled layer-1 precompute. 16 nodes per block, W1 slice in smem.
// Thread: m = tid&127, g = tid>>7; handles 8 nodes (4 f32x2 pairs) at dim m.
// Also: block 0 / thread 0 performs edge-index dtype detection.
// smem: w1s[100*128] + xsh2[100*16] (k-major, node-minor) = 57.6 KB
// ---------------------------------------------------------------------------
#define NB 16
__global__ void __launch_bounds__(256, 3)
node_precompute(const float* __restrict__ xd,
                const float* __restrict__ xs,
                const float* __restrict__ W1,
                const float* __restrict__ b1,
                const long long* __restrict__ ell,
                int n_drug, int n_dis, int nb_drug) {
    extern __shared__ float nsm[];
    float* w1s  = nsm;              // 100*128
    float* xsh2 = nsm + 12800;      // 100*16, [k][node]

    const int tid = threadIdx.x;
    const int bid = blockIdx.x;

    if (bid == 0 && tid == 0) {
        int ok64 = 1;
#pragma unroll
        for (int t = 0; t < 8; t++) {
            long long v = ell[t];
            if (v < 0 || v >= 1000000) ok64 = 0;
        }
        g_idx64 = ok64;
    }

    const bool is_drug = bid < nb_drug;
    const int  n       = is_drug ? n_drug : n_dis;
    const int  nbase   = (is_drug ? bid : bid - nb_drug) * NB;
    const float* x   = is_drug ? xd : xs;
    const float* w   = W1 + (is_drug ? 0 : 100 * 128);
    float*       out = is_drug ? g_hd : g_he;

    for (int i = tid; i < 100 * 128; i += 256) w1s[i] = w[i];
    for (int i = tid; i < NB * 100; i += 256) {
        int node = i & (NB - 1);
        int k    = i >> 4;
        int gn   = nbase + node;
        xsh2[k * NB + node] = (gn < n) ? x[(long)gn * 100 + k] : 0.0f;
    }
    __syncthreads();

    const int m = tid & 127;
    const int g = tid >> 7;           // 0..1 -> nodes 8g..8g+7

    float bm = is_drug ? b1[m] : 0.0f;
    unsigned long long acc[4];
#pragma unroll
    for (int p = 0; p < 4; p++) acc[p] = pk2(bm, bm);

#pragma unroll 4
    for (int k = 0; k < 100; k++) {
        float wv = w1s[k * 128 + m];
        unsigned long long w2 = pk2(wv, wv);
        float4 xa = *(const float4*)&xsh2[k * NB + 8 * g];
        float4 xb = *(const float4*)&xsh2[k * NB + 8 * g + 4];
        acc[0] = fma2(pk2(xa.x, xa.y), w2, acc[0]);
        acc[1] = fma2(pk2(xa.z, xa.w), w2, acc[1]);
        acc[2] = fma2(pk2(xb.x, xb.y), w2, acc[2]);
        acc[3] = fma2(pk2(xb.z, xb.w), w2, acc[3]);
    }

#pragma unroll
    for (int p = 0; p < 4; p++) {
        float a, b;
        up2(acc[p], a, b);
        int n0 = nbase + 8 * g + 2 * p;
        if (n0 < n)     out[(long)n0 * 128 + m]       = a;
        if (n0 + 1 < n) out[(long)(n0 + 1) * 128 + m] = b;
    }
}

// ---------------------------------------------------------------------------
// Kernel 2: persistent per-edge MLP. Block = 256 threads, tile = 128 edges,
// loops over tiles. Weights staged in smem once per block.
// Phase 1: gather h_drug[i]+h_disease[j], leaky, stage in hs (XOR-swizzled).
// Phase 2: [128e x 32m] GEMM (K=128) f32x2 FMAs, 4e x 4m thread tile.
// Phase 3: 32->16->1 per edge (thread-per-edge).
// ---------------------------------------------------------------------------
#define EPB        128
#define NTHR       256
#define O2_STRIDE  33

// smem layout (floats)
#define OFF_HS   0
#define OFF_WS2  (OFF_HS  + EPB * 128)             // 16384
#define OFF_O2   (OFF_WS2 + 128 * 32)              // 20480
#define OFF_W3   (OFF_O2  + EPB * O2_STRIDE)       // 24704
#define OFF_W4   (OFF_W3  + 32 * 16)               // 25216
#define OFF_B2   (OFF_W4  + 16)                    // 25232
#define OFF_B3   (OFF_B2  + 32)                    // 25264
#define SMEM_FLOATS (OFF_B3 + 16)                  // 25280
#define SMEM_BYTES (SMEM_FLOATS * 4)               // 101120

__global__ void __launch_bounds__(NTHR, 2)
edge_mlp_kernel(const void* __restrict__ ell,
                const float* __restrict__ W2, const float* __restrict__ b2,
                const float* __restrict__ W3, const float* __restrict__ b3,
                const float* __restrict__ W4, const float* __restrict__ b4,
                float* __restrict__ out, int E, int n_tiles) {
    extern __shared__ float sm[];
    float* hs  = sm + OFF_HS;
    float* ws2 = sm + OFF_WS2;
    float* o2  = sm + OFF_O2;
    float* w3s = sm + OFF_W3;
    float* w4s = sm + OFF_W4;
    float* b2s = sm + OFF_B2;
    float* b3s = sm + OFF_B3;

    const int tid  = threadIdx.x;
    const int warp = tid >> 5;
    const int lane = tid & 31;
    const int is64 = g_idx64;

    // ---- stage weights once ----
    for (int i = tid; i < 128 * 32; i += NTHR) ws2[i] = W2[i];
    for (int i = tid; i < 32 * 16;  i += NTHR) w3s[i] = W3[i];
    if (tid < 16) w4s[tid] = W4[tid];
    if (tid < 32) b2s[tid] = b2[tid];
    if (tid < 16) b3s[tid] = b3[tid];

    const float b4v = __ldg(&b4[0]);

    // phase-2 constants
    const int te   = tid >> 3;       // 0..31
    const int tm   = tid & 7;        // 0..7
    const int tesw = te & 7;         // XOR swizzle key

    for (int tile = blockIdx.x; tile < n_tiles; tile += gridDim.x) {
        // ---- phase 1: gather + combine (8 warps x 16 edges) ----
        {
            int ebase = tile * EPB + warp * 16;
            int e  = ebase + (lane & 15);
            int ec = e < E ? e : (E - 1);
            long long pos = (lane < 16) ? (long long)ec : (long long)E + ec;
            long long v = load_idx(ell, pos, is64);

#pragma unroll
            for (int t = 0; t < 16; t++) {
                long long i = __shfl_sync(0xffffffffu, v, t);
                long long j = __shfl_sync(0xffffffffu, v, 16 + t);
                int er = warp * 16 + t;
                const float4 a = *(const float4*)&g_hd[i * 128 + lane * 4];
                const float4 b = *(const float4*)&g_he[j * 128 + lane * 4];
                float4 s;
                s.x = lrelu(a.x + b.x);
                s.y = lrelu(a.y + b.y);
                s.z = lrelu(a.z + b.z);
                s.w = lrelu(a.w + b.w);
                // XOR-swizzled store: unit = lane, key = (er>>2)&7
                int col = (lane ^ ((er >> 2) & 7)) << 2;
                *(float4*)&hs[er * 128 + col] = s;
            }
        }
        __syncthreads();

        // ---- phase 2: 128x32 GEMM, 4e x 4m per thread ----
        {
            const float* h0 = hs + (4 * te + 0) * 128;
            const float* h1 = hs + (4 * te + 1) * 128;
            const float* h2 = hs + (4 * te + 2) * 128;
            const float* h3 = hs + (4 * te + 3) * 128;

            unsigned long long acc[4][2];
#pragma unroll
            for (int r = 0; r < 4; r++) { acc[r][0] = 0ull; acc[r][1] = 0ull; }

#pragma unroll 4
            for (int k = 0; k < 128; k += 4) {
                ulonglong2 w0  = *(const ulonglong2*)&ws2[(k + 0) * 32 + 4 * tm];
                ulonglong2 w1  = *(const ulonglong2*)&ws2[(k + 1) * 32 + 4 * tm];
                ulonglong2 w2  = *(const ulonglong2*)&ws2[(k + 2) * 32 + 4 * tm];
                ulonglong2 w3v = *(const ulonglong2*)&ws2[(k + 3) * 32 + 4 * tm];

                int col = (((k >> 2) ^ tesw) << 2);  // swizzled 16B unit
                float4 hv;
                unsigned long long hb;
#pragma unroll
                for (int r = 0; r < 4; r++) {
                    const float* hp = (r == 0) ? h0 : (r == 1) ? h1
                                    : (r == 2) ? h2 : h3;
                    hv = *(const float4*)&hp[col];
                    hb = pk2(hv.x, hv.x);
                    acc[r][0] = fma2(hb, w0.x, acc[r][0]);
                    acc[r][1] = fma2(hb, w0.y, acc[r][1]);
                    hb = pk2(hv.y, hv.y);
                    acc[r][0] = fma2(hb, w1.x, acc[r][0]);
                    acc[r][1] = fma2(hb, w1.y, acc[r][1]);
                    hb = pk2(hv.z, hv.z);
                    acc[r][0] = fma2(hb, w2.x, acc[r][0]);
                    acc[r][1] = fma2(hb, w2.y, acc[r][1]);
                    hb = pk2(hv.w, hv.w);
                    acc[r][0] = fma2(hb, w3v.x, acc[r][0]);
                    acc[r][1] = fma2(hb, w3v.y, acc[r][1]);
                }
            }

            // epilogue: +b2, leaky, stash
#pragma unroll
            for (int r = 0; r < 4; r++) {
                int er = 4 * te + r;
#pragma unroll
                for (int p = 0; p < 2; p++) {
                    float a, b;
                    up2(acc[r][p], a, b);
                    int m0 = 4 * tm + 2 * p;
                    o2[er * O2_STRIDE + m0 + 0] = lrelu(a + b2s[m0 + 0]);
                    o2[er * O2_STRIDE + m0 + 1] = lrelu(b + b2s[m0 + 1]);
                }
            }
        }
        __syncthreads();

        // ---- phase 3: layers 3 (32->16, leaky) and 4 (16->1) ----
        if (tid < EPB) {
            int eg = tile * EPB + tid;
            unsigned long long a3[8];
#pragma unroll
            for (int p = 0; p < 8; p++) a3[p] = pk2(b3s[2 * p], b3s[2 * p + 1]);

            const float* row = o2 + tid * O2_STRIDE;
#pragma unroll 4
            for (int k2 = 0; k2 < 32; k2++) {
                float xv = row[k2];
                unsigned long long xb = pk2(xv, xv);
                const ulonglong2 wA = *(const ulonglong2*)&w3s[k2 * 16 + 0];
                const ulonglong2 wB = *(const ulonglong2*)&w3s[k2 * 16 + 4];
                const ulonglong2 wC = *(const ulonglong2*)&w3s[k2 * 16 + 8];
                const ulonglong2 wD = *(const ulonglong2*)&w3s[k2 * 16 + 12];
                a3[0] = fma2(xb, wA.x, a3[0]);
                a3[1] = fma2(xb, wA.y, a3[1]);
                a3[2] = fma2(xb, wB.x, a3[2]);
                a3[3] = fma2(xb, wB.y, a3[3]);
                a3[4] = fma2(xb, wC.x, a3[4]);
                a3[5] = fma2(xb, wC.y, a3[5]);
                a3[6] = fma2(xb, wD.x, a3[6]);
                a3[7] = fma2(xb, wD.y, a3[7]);
            }

            float y = b4v;
#pragma unroll
            for (int p = 0; p < 8; p++) {
                float a, b;
                up2(a3[p], a, b);
                y = fmaf(lrelu(a), w4s[2 * p + 0], y);
                y = fmaf(lrelu(b), w4s[2 * p + 1], y);
            }
            if (eg < E) out[eg] = y;
        }
        __syncthreads();
    }
}

// ---------------------------------------------------------------------------
extern "C" void kernel_launch(void* const* d_in, const int* in_sizes, int n_in,
                              void* d_out, int out_size) {
    const float* xd  = (const float*)d_in[0];
    const float* xs  = (const float*)d_in[1];
    const void*  ell = d_in[2];
    const float* W1  = (const float*)d_in[3];
    const float* b1  = (const float*)d_in[4];
    const float* W2  = (const float*)d_in[5];
    const float* b2  = (const float*)d_in[6];
    const float* W3  = (const float*)d_in[7];
    const float* b3  = (const float*)d_in[8];
    const float* W4  = (const float*)d_in[9];
    const float* b4  = (const float*)d_in[10];
    float* out = (float*)d_out;

    int n_drug = in_sizes[0] / 100;
    int n_dis  = in_sizes[1] / 100;
    int E      = in_sizes[2] / 2;

    int nb_drug = (n_drug + NB - 1) / NB;
    int nb_dis  = (n_dis  + NB - 1) / NB;
    int node_smem = (12800 + 100 * NB) * 4;
    cudaFuncSetAttribute(node_precompute,
                         cudaFuncAttributeMaxDynamicSharedMemorySize, node_smem);
    node_precompute<<<nb_drug + nb_dis, 256, node_smem>>>(
        xd, xs, W1, b1, (const long long*)ell, n_drug, n_dis, nb_drug);

    cudaFuncSetAttribute(edge_mlp_kernel,
                         cudaFuncAttributeMaxDynamicSharedMemorySize, SMEM_BYTES);
    int n_tiles = (E + EPB - 1) / EPB;
    int grid = 2 * 148;
    if (grid > n_tiles) grid = n_tiles;
    edge_mlp_kernel<<<grid, NTHR, SMEM_BYTES>>>(ell, W2, b2, W3, b3, W4, b4,
                                                out, E, n_tiles);
}

// round 4
// speedup vs baseline: 1.3870x; 1.3870x over previous
#include <cuda_runtime.h>
#include <cuda_bf16.h>

// ---------------------------------------------------------------------------
// Classifier: out[e] = MLP(concat(x_drug[i_e], x_disease[j_e]))
// Layer-1 factored per-node:
//   h_drug    = x_drug    @ W1[0:100]   + b1     (n_drug x 128)
//   h_disease = x_disease @ W1[100:200]          (n_dis  x 128)
// per edge: h = leaky(h_drug[i] + h_disease[j]); then 128->32->16->1.
// ---------------------------------------------------------------------------

typedef unsigned long long ull;

#define MAX_NODES 16384
__device__ float g_hd[MAX_NODES * 128];
__device__ float g_he[MAX_NODES * 128];
__device__ int   g_idx64;   // 1 if edge index buffer is int64, 0 if int32

__device__ __forceinline__ float lrelu(float v) {
    return v >= 0.0f ? v : 0.01f * v;
}

__device__ __forceinline__ ull pk2(float a, float b) {
    ull r;
    asm("mov.b64 %0, {%1, %2};" : "=l"(r) : "f"(a), "f"(b));
    return r;
}
__device__ __forceinline__ void up2(ull v, float& a, float& b) {
    asm("mov.b64 {%0, %1}, %2;" : "=f"(a), "=f"(b) : "l"(v));
}
__device__ __forceinline__ ull fma2(ull a, ull b, ull c) {
    ull d;
    asm("fma.rn.f32x2 %0, %1, %2, %3;" : "=l"(d) : "l"(a), "l"(b), "l"(c));
    return d;
}

__device__ __forceinline__ long long load_idx(const void* ell, long long pos,
                                              int is64) {
    if (is64) return ((const long long*)ell)[pos];
    return (long long)((const int*)ell)[pos];
}

// ---------------------------------------------------------------------------
// Kernel 1: tiled layer-1 precompute (16 nodes/block, W1 slice in smem).
// Block 0 thread 0 also detects the edge-index dtype (JAX w/o x64 emits int32).
// ---------------------------------------------------------------------------
#define NB 16
__global__ void __launch_bounds__(256, 3)
node_precompute(const float* __restrict__ xd,
                const float* __restrict__ xs,
                const float* __restrict__ W1,
                const float* __restrict__ b1,
                const long long* __restrict__ ell,
                int n_drug, int n_dis, int nb_drug) {
    extern __shared__ float nsm[];
    float* w1s  = nsm;              // 100*128
    float* xsh2 = nsm + 12800;      // 100*16, [k][node]

    const int tid = threadIdx.x;
    const int bid = blockIdx.x;

    if (bid == 0 && tid == 0) {
        int ok64 = 1;
#pragma unroll
        for (int t = 0; t < 8; t++) {
            long long v = ell[t];
            if (v < 0 || v >= 1000000) ok64 = 0;
        }
        g_idx64 = ok64;
    }

    const bool is_drug = bid < nb_drug;
    const int  n       = is_drug ? n_drug : n_dis;
    const int  nbase   = (is_drug ? bid : bid - nb_drug) * NB;
    const float* x   = is_drug ? xd : xs;
    const float* w   = W1 + (is_drug ? 0 : 100 * 128);
    float*       out = is_drug ? g_hd : g_he;

    for (int i = tid; i < 100 * 128; i += 256) w1s[i] = w[i];
    for (int i = tid; i < NB * 100; i += 256) {
        int node = i & (NB - 1);
        int k    = i >> 4;
        int gn   = nbase + node;
        xsh2[k * NB + node] = (gn < n) ? x[(long)gn * 100 + k] : 0.0f;
    }
    __syncthreads();

    const int m = tid & 127;
    const int g = tid >> 7;

    float bm = is_drug ? b1[m] : 0.0f;
    ull acc[4];
#pragma unroll
    for (int p = 0; p < 4; p++) acc[p] = pk2(bm, bm);

#pragma unroll 4
    for (int k = 0; k < 100; k++) {
        float wv = w1s[k * 128 + m];
        ull w2 = pk2(wv, wv);
        float4 xa = *(const float4*)&xsh2[k * NB + 8 * g];
        float4 xb = *(const float4*)&xsh2[k * NB + 8 * g + 4];
        acc[0] = fma2(pk2(xa.x, xa.y), w2, acc[0]);
        acc[1] = fma2(pk2(xa.z, xa.w), w2, acc[1]);
        acc[2] = fma2(pk2(xb.x, xb.y), w2, acc[2]);
        acc[3] = fma2(pk2(xb.z, xb.w), w2, acc[3]);
    }

#pragma unroll
    for (int p = 0; p < 4; p++) {
        float a, b;
        up2(acc[p], a, b);
        int n0 = nbase + 8 * g + 2 * p;
        if (n0 < n)     out[(long)n0 * 128 + m]       = a;
        if (n0 + 1 < n) out[(long)(n0 + 1) * 128 + m] = b;
    }
}

// ---------------------------------------------------------------------------
// Kernel 2: persistent per-edge MLP. 512 threads, tile = 128 edges.
// Phase 1: gather (warp = 8 edges), leaky, store hs row-swizzled (key=(e>>1)&7).
// Phase 2: 128e x 32m GEMM K=128; thread = 2 edges x 1 m-quad (2 m-pairs).
//          Weights pre-interleaved in smem as (k,k+1)-paired m-pair ulls ->
//          zero packing MOVs on the weight side; h duplicated via pk2.
// Phase 3: 32->16->1 per edge (tid<128).
// ---------------------------------------------------------------------------
#define EPB        128
#define NTHR       512
#define O2_STRIDE  33

// smem layout (floats)
#define OFF_HS   0                                  // 128*128 = 16384
#define OFF_WI   16384                              // ws2i: 2048 ull = 4096 f
#define OFF_O2   20480                              // 128*33 = 4224
#define OFF_W3   24704                              // 512
#define OFF_W4   25216                              // 16
#define OFF_B2   25232                              // 32
#define OFF_B3   25264                              // 16
#define SMEM_FLOATS 25280
#define SMEM_BYTES (SMEM_FLOATS * 4)                // 101120

__global__ void __launch_bounds__(NTHR, 2)
edge_mlp_kernel(const void* __restrict__ ell,
                const float* __restrict__ W2, const float* __restrict__ b2,
                const float* __restrict__ W3, const float* __restrict__ b3,
                const float* __restrict__ W4, const float* __restrict__ b4,
                float* __restrict__ out, int E, int n_tiles) {
    extern __shared__ float sm[];
    float* hs  = sm + OFF_HS;
    ull*   wsi = (ull*)(sm + OFF_WI);
    float* o2  = sm + OFF_O2;
    float* w3s = sm + OFF_W3;
    float* w4s = sm + OFF_W4;
    float* b2s = sm + OFF_B2;
    float* b3s = sm + OFF_B3;

    const int tid  = threadIdx.x;
    const int warp = tid >> 5;
    const int lane = tid & 31;
    const int is64 = g_idx64;

    // ---- stage weights once ----
    // ws2i element (k2, mp, parity) = (W2[2k2+parity][2mp], W2[2k2+parity][2mp+1])
    // linear ull index = k2*32 + mp*2 + parity
    for (int idx = tid; idx < 2048; idx += NTHR) {
        int parity = idx & 1;
        int mp     = (idx >> 1) & 15;
        int k2     = idx >> 5;
        int k      = 2 * k2 + parity;
        wsi[idx] = pk2(W2[k * 32 + 2 * mp], W2[k * 32 + 2 * mp + 1]);
    }
    for (int i = tid; i < 32 * 16; i += NTHR) w3s[i] = W3[i];
    if (tid < 16) w4s[tid] = W4[tid];
    if (tid < 32) b2s[tid] = b2[tid];
    if (tid < 16) b3s[tid] = b3[tid];

    const float b4v = __ldg(&b4[0]);

    // phase-2 lane mapping: warp covers 8 edge-pairs x 4 m-quads
    const int ep  = 8 * (warp & 7) + (lane & 7);     // 0..63
    const int tm  = (lane >> 3) + 4 * (warp >> 3);   // 0..7 (m quad)
    const int e0  = 2 * ep;
    const int key = ep & 7;                          // = (e0>>1)&7 = (e1>>1)&7
    const float* hrow0 = hs + e0 * 128;
    const float* hrow1 = hs + (e0 + 1) * 128;
    const ull*   wbase = wsi + 4 * tm;               // mp = 2tm at k2*32

    for (int tile = blockIdx.x; tile < n_tiles; tile += gridDim.x) {
        // ---- phase 1: gather + combine (16 warps x 8 edges) ----
        {
            int ebase = tile * EPB + warp * 8;
            int e  = ebase + (lane & 7);
            int ec = e < E ? e : (E - 1);
            long long pos = (lane & 8) ? (long long)E + ec : (long long)ec;
            long long v = load_idx(ell, pos, is64);

#pragma unroll
            for (int t = 0; t < 8; t++) {
                long long i = __shfl_sync(0xffffffffu, v, t);
                long long j = __shfl_sync(0xffffffffu, v, 8 + t);
                int er = warp * 8 + t;
                const float4 a = *(const float4*)&g_hd[i * 128 + lane * 4];
                const float4 b = *(const float4*)&g_he[j * 128 + lane * 4];
                float4 s;
                s.x = lrelu(a.x + b.x);
                s.y = lrelu(a.y + b.y);
                s.z = lrelu(a.z + b.z);
                s.w = lrelu(a.w + b.w);
                int col = (lane ^ ((er >> 1) & 7)) << 2;   // row-swizzled unit
                *(float4*)&hs[er * 128 + col] = s;
            }
        }
        __syncthreads();

        // ---- phase 2: K=128 GEMM; acc = m-pair f32x2, 2 edges x 2 pairs ----
        {
            ull acc00 = 0, acc01 = 0, acc10 = 0, acc11 = 0;

#pragma unroll 2
            for (int i = 0; i < 32; i++) {            // k = 4i .. 4i+3
                int u = ((i ^ key) & 7) | (i & ~7);   // swizzle low 3 bits
                const float4 h0 = *(const float4*)&hrow0[u << 2];
                const float4 h1 = *(const float4*)&hrow1[u << 2];
                const ulonglong2 wA0 = *(const ulonglong2*)&wbase[(2 * i) * 32];
                const ulonglong2 wB0 = *(const ulonglong2*)&wbase[(2 * i) * 32 + 2];
                const ulonglong2 wA1 = *(const ulonglong2*)&wbase[(2 * i + 1) * 32];
                const ulonglong2 wB1 = *(const ulonglong2*)&wbase[(2 * i + 1) * 32 + 2];
                ull d;
                d = pk2(h0.x, h0.x); acc00 = fma2(d, wA0.x, acc00); acc01 = fma2(d, wB0.x, acc01);
                d = pk2(h1.x, h1.x); acc10 = fma2(d, wA0.x, acc10); acc11 = fma2(d, wB0.x, acc11);
                d = pk2(h0.y, h0.y); acc00 = fma2(d, wA0.y, acc00); acc01 = fma2(d, wB0.y, acc01);
                d = pk2(h1.y, h1.y); acc10 = fma2(d, wA0.y, acc10); acc11 = fma2(d, wB0.y, acc11);
                d = pk2(h0.z, h0.z); acc00 = fma2(d, wA1.x, acc00); acc01 = fma2(d, wB1.x, acc01);
                d = pk2(h1.z, h1.z); acc10 = fma2(d, wA1.x, acc10); acc11 = fma2(d, wB1.x, acc11);
                d = pk2(h0.w, h0.w); acc00 = fma2(d, wA1.y, acc00); acc01 = fma2(d, wB1.y, acc01);
                d = pk2(h1.w, h1.w); acc10 = fma2(d, wA1.y, acc10); acc11 = fma2(d, wB1.y, acc11);
            }

            // epilogue: +b2, leaky -> o2
            float a, b;
            int m0 = 4 * tm;
            up2(acc00, a, b);
            o2[e0 * O2_STRIDE + m0 + 0] = lrelu(a + b2s[m0 + 0]);
            o2[e0 * O2_STRIDE + m0 + 1] = lrelu(b + b2s[m0 + 1]);
            up2(acc01, a, b);
            o2[e0 * O2_STRIDE + m0 + 2] = lrelu(a + b2s[m0 + 2]);
            o2[e0 * O2_STRIDE + m0 + 3] = lrelu(b + b2s[m0 + 3]);
            up2(acc10, a, b);
            o2[(e0 + 1) * O2_STRIDE + m0 + 0] = lrelu(a + b2s[m0 + 0]);
            o2[(e0 + 1) * O2_STRIDE + m0 + 1] = lrelu(b + b2s[m0 + 1]);
            up2(acc11, a, b);
            o2[(e0 + 1) * O2_STRIDE + m0 + 2] = lrelu(a + b2s[m0 + 2]);
            o2[(e0 + 1) * O2_STRIDE + m0 + 3] = lrelu(b + b2s[m0 + 3]);
        }
        __syncthreads();

        // ---- phase 3: layers 3 (32->16, leaky) and 4 (16->1) ----
        if (tid < EPB) {
            int eg = tile * EPB + tid;
            ull a3[8];
#pragma unroll
            for (int p = 0; p < 8; p++) a3[p] = pk2(b3s[2 * p], b3s[2 * p + 1]);

            const float* row = o2 + tid * O2_STRIDE;
#pragma unroll 4
            for (int k2 = 0; k2 < 32; k2++) {
                float xv = row[k2];
                ull xb = pk2(xv, xv);
                const ulonglong2 wA = *(const ulonglong2*)&w3s[k2 * 16 + 0];
                const ulonglong2 wB = *(const ulonglong2*)&w3s[k2 * 16 + 4];
                const ulonglong2 wC = *(const ulonglong2*)&w3s[k2 * 16 + 8];
                const ulonglong2 wD = *(const ulonglong2*)&w3s[k2 * 16 + 12];
                a3[0] = fma2(xb, wA.x, a3[0]);
                a3[1] = fma2(xb, wA.y, a3[1]);
                a3[2] = fma2(xb, wB.x, a3[2]);
                a3[3] = fma2(xb, wB.y, a3[3]);
                a3[4] = fma2(xb, wC.x, a3[4]);
                a3[5] = fma2(xb, wC.y, a3[5]);
                a3[6] = fma2(xb, wD.x, a3[6]);
                a3[7] = fma2(xb, wD.y, a3[7]);
            }

            float y = b4v;
#pragma unroll
            for (int p = 0; p < 8; p++) {
                float a, b;
                up2(a3[p], a, b);
                y = fmaf(lrelu(a), w4s[2 * p + 0], y);
                y = fmaf(lrelu(b), w4s[2 * p + 1], y);
            }
            if (eg < E) out[eg] = y;
        }
        __syncthreads();
    }
}

// ---------------------------------------------------------------------------
extern "C" void kernel_launch(void* const* d_in, const int* in_sizes, int n_in,
                              void* d_out, int out_size) {
    const float* xd  = (const float*)d_in[0];
    const float* xs  = (const float*)d_in[1];
    const void*  ell = d_in[2];
    const float* W1  = (const float*)d_in[3];
    const float* b1  = (const float*)d_in[4];
    const float* W2  = (const float*)d_in[5];
    const float* b2  = (const float*)d_in[6];
    const float* W3  = (const float*)d_in[7];
    const float* b3  = (const float*)d_in[8];
    const float* W4  = (const float*)d_in[9];
    const float* b4  = (const float*)d_in[10];
    float* out = (float*)d_out;

    int n_drug = in_sizes[0] / 100;
    int n_dis  = in_sizes[1] / 100;
    int E      = in_sizes[2] / 2;

    int nb_drug = (n_drug + NB - 1) / NB;
    int nb_dis  = (n_dis  + NB - 1) / NB;
    int node_smem = (12800 + 100 * NB) * 4;
    cudaFuncSetAttribute(node_precompute,
                         cudaFuncAttributeMaxDynamicSharedMemorySize, node_smem);
    node_precompute<<<nb_drug + nb_dis, 256, node_smem>>>(
        xd, xs, W1, b1, (const long long*)ell, n_drug, n_dis, nb_drug);

    cudaFuncSetAttribute(edge_mlp_kernel,
                         cudaFuncAttributeMaxDynamicSharedMemorySize, SMEM_BYTES);
    int n_tiles = (E + EPB - 1) / EPB;
    int grid = 2 * 148;
    if (grid > n_tiles) grid = n_tiles;
    edge_mlp_kernel<<<grid, NTHR, SMEM_BYTES>>>(ell, W2, b2, W3, b3, W4, b4,
                                                out, E, n_tiles);
}

// round 6
// speedup vs baseline: 1.9047x; 1.3732x over previous
#include <cuda_runtime.h>
#include <cuda_bf16.h>
#include <cstdint>

// ---------------------------------------------------------------------------
// Classifier: out[e] = MLP(concat(x_drug[i_e], x_disease[j_e]))
// Layer-1 factored per-node (fp32):
//   h_drug    = x_drug    @ W1[0:100]   + b1     (n_drug x 128)
//   h_disease = x_disease @ W1[100:200]          (n_dis  x 128)
// Per edge: h = leaky(h_drug[i]+h_disease[j]); layer-2 (128->32) on
// mma.sync.m16n8k8 tf32; layers 3/4 (32->16->1) fp32 in registers with
// shfl reductions. Warp-autonomous: no per-tile block syncs.
// ---------------------------------------------------------------------------

typedef unsigned long long ull;

#define MAX_NODES 16384
__device__ float g_hd[MAX_NODES * 128];
__device__ float g_he[MAX_NODES * 128];
__device__ int   g_idx64;   // 1 if edge index buffer is int64, 0 if int32

__device__ __forceinline__ float lrelu(float v) {
    return v >= 0.0f ? v : 0.01f * v;
}
__device__ __forceinline__ ull pk2(float a, float b) {
    ull r;
    asm("mov.b64 %0, {%1, %2};" : "=l"(r) : "f"(a), "f"(b));
    return r;
}
__device__ __forceinline__ void up2(ull v, float& a, float& b) {
    asm("mov.b64 {%0, %1}, %2;" : "=f"(a), "=f"(b) : "l"(v));
}
__device__ __forceinline__ ull fma2(ull a, ull b, ull c) {
    ull d;
    asm("fma.rn.f32x2 %0, %1, %2, %3;" : "=l"(d) : "l"(a), "l"(b), "l"(c));
    return d;
}
__device__ __forceinline__ ull add2(ull a, ull b) {
    ull d;
    asm("add.rn.f32x2 %0, %1, %2;" : "=l"(d) : "l"(a), "l"(b));
    return d;
}
__device__ __forceinline__ uint32_t f2tf32(float f) {
    uint32_t r;
    asm("cvt.rna.tf32.f32 %0, %1;" : "=r"(r) : "f"(f));
    return r;
}
__device__ __forceinline__ long long load_idx(const void* ell, long long pos,
                                              int is64) {
    if (is64) return ((const long long*)ell)[pos];
    return (long long)((const int*)ell)[pos];
}

// m16n8k8 tf32 MMA (row.col), D/C fp32 in-place accumulate
__device__ __forceinline__ void mma8(float d[4], uint32_t a0, uint32_t a1,
                                     uint32_t a2, uint32_t a3,
                                     uint32_t b0, uint32_t b1) {
    asm volatile(
        "mma.sync.aligned.m16n8k8.row.col.f32.tf32.tf32.f32 "
        "{%0,%1,%2,%3}, {%4,%5,%6,%7}, {%8,%9}, {%0,%1,%2,%3};"
        : "+f"(d[0]), "+f"(d[1]), "+f"(d[2]), "+f"(d[3])
        : "r"(a0), "r"(a1), "r"(a2), "r"(a3), "r"(b0), "r"(b1));
}

// ---------------------------------------------------------------------------
// Kernel 1: tiled layer-1 precompute (16 nodes/block, W1 slice in smem).
// Block 0 thread 0 also detects the edge-index dtype (JAX w/o x64 -> int32).
// ---------------------------------------------------------------------------
#define NB 16
__global__ void __launch_bounds__(256, 3)
node_precompute(const float* __restrict__ xd,
                const float* __restrict__ xs,
                const float* __restrict__ W1,
                const float* __restrict__ b1,
                const long long* __restrict__ ell,
                int n_drug, int n_dis, int nb_drug) {
    extern __shared__ float nsm[];
    float* w1s  = nsm;              // 100*128
    float* xsh2 = nsm + 12800;      // 100*16, [k][node]

    const int tid = threadIdx.x;
    const int bid = blockIdx.x;

    if (bid == 0 && tid == 0) {
        int ok64 = 1;
#pragma unroll
        for (int t = 0; t < 8; t++) {
            long long v = ell[t];
            if (v < 0 || v >= 1000000) ok64 = 0;
        }
        g_idx64 = ok64;
    }

    const bool is_drug = bid < nb_drug;
    const int  n       = is_drug ? n_drug : n_dis;
    const int  nbase   = (is_drug ? bid : bid - nb_drug) * NB;
    const float* x   = is_drug ? xd : xs;
    const float* w   = W1 + (is_drug ? 0 : 100 * 128);
    float*       out = is_drug ? g_hd : g_he;

    for (int i = tid; i < 100 * 128; i += 256) w1s[i] = w[i];
    for (int i = tid; i < NB * 100; i += 256) {
        int node = i & (NB - 1);
        int k    = i >> 4;
        int gn   = nbase + node;
        xsh2[k * NB + node] = (gn < n) ? x[(long)gn * 100 + k] : 0.0f;
    }
    __syncthreads();

    const int m = tid & 127;
    const int g = tid >> 7;

    float bm = is_drug ? b1[m] : 0.0f;
    ull acc[4];
#pragma unroll
    for (int p = 0; p < 4; p++) acc[p] = pk2(bm, bm);

#pragma unroll 4
    for (int k = 0; k < 100; k++) {
        float wv = w1s[k * 128 + m];
        ull w2 = pk2(wv, wv);
        float4 xa = *(const float4*)&xsh2[k * NB + 8 * g];
        float4 xb = *(const float4*)&xsh2[k * NB + 8 * g + 4];
        acc[0] = fma2(pk2(xa.x, xa.y), w2, acc[0]);
        acc[1] = fma2(pk2(xa.z, xa.w), w2, acc[1]);
        acc[2] = fma2(pk2(xb.x, xb.y), w2, acc[2]);
        acc[3] = fma2(pk2(xb.z, xb.w), w2, acc[3]);
    }

#pragma unroll
    for (int p = 0; p < 4; p++) {
        float a, b;
        up2(acc[p], a, b);
        int n0 = nbase + 8 * g + 2 * p;
        if (n0 < n)     out[(long)n0 * 128 + m]       = a;
        if (n0 + 1 < n) out[(long)(n0 + 1) * 128 + m] = b;
    }
}

// ---------------------------------------------------------------------------
// Kernel 2: persistent per-edge MLP, warp-autonomous.
// Block = 256 threads (8 warps), tile = 128 edges, warp owns 16 edges.
//  hs    : per-warp 16 rows x 128 tf32 (stride 132 -> conflict-free A frags)
//  bfrag : W2 tf32 pre-arranged as mma B fragments [16 kstep][4 nb][lane][2]
// ---------------------------------------------------------------------------
#define EPB   128
#define NTHR  256
#define HS_STRIDE 132

// smem byte offsets
#define OFF_HS   0                        // 128*132*4 = 67584
#define OFF_BF   67584                    // 4096 f = 16384 B
#define OFF_W3   83968                    // 512 f = 2048 B
#define OFF_W4   86016                    // 16 f = 64 B
#define OFF_B2   86080                    // 32 f = 128 B
#define OFF_B3   86208                    // 16 f = 64 B
#define SMEM_BYTES 86272

__global__ void __launch_bounds__(NTHR, 2)
edge_mlp_kernel(const void* __restrict__ ell,
                const float* __restrict__ W2, const float* __restrict__ b2,
                const float* __restrict__ W3, const float* __restrict__ b3,
                const float* __restrict__ W4, const float* __restrict__ b4,
                float* __restrict__ out, int E, int n_tiles) {
    extern __shared__ char smem[];
    uint32_t* hsu  = (uint32_t*)(smem + OFF_HS);
    uint32_t* bfr  = (uint32_t*)(smem + OFF_BF);
    float*    w3s  = (float*)(smem + OFF_W3);
    float*    w4s  = (float*)(smem + OFF_W4);
    float*    b2s  = (float*)(smem + OFF_B2);
    float*    b3s  = (float*)(smem + OFF_B3);

    const int tid  = threadIdx.x;
    const int warp = tid >> 5;
    const int lane = tid & 31;
    const int is64 = g_idx64;

    // ---- stage weights once ----
    // bfrag layout: idx = (((ks*4 + nb)*32 + lane)*2 + r)
    //   value = tf32(W2[(ks*8 + lane%4 + 4r) * 32 + nb*8 + lane/4])
    for (int idx = tid; idx < 4096; idx += NTHR) {
        int r  = idx & 1;
        int ln = (idx >> 1) & 31;
        int nb = (idx >> 6) & 3;
        int ks = idx >> 8;
        int k  = ks * 8 + (ln & 3) + 4 * r;
        int n  = nb * 8 + (ln >> 2);
        bfr[idx] = f2tf32(W2[k * 32 + n]);
    }
    for (int i = tid; i < 32 * 16; i += NTHR) w3s[i] = W3[i];
    if (tid < 16) w4s[tid] = W4[tid];
    if (tid < 32) b2s[tid] = b2[tid];
    if (tid < 16) b3s[tid] = b3[tid];
    __syncthreads();

    const float b4v = __ldg(&b4[0]);

    // per-warp pointers
    uint32_t* hw = hsu + warp * 16 * HS_STRIDE;
    const int g = lane >> 2;          // 0..7  (edge row within half-stripe)
    const int c = lane & 3;           // 0..3
    const uint32_t* r0 = hw + g * HS_STRIDE;
    const uint32_t* r1 = r0 + 8 * HS_STRIDE;
    const uint2* bfl = (const uint2*)bfr + lane;   // stride 32 uint2 per (ks,nb)

    for (int tile = blockIdx.x; tile < n_tiles; tile += gridDim.x) {
        // ---- phase 1: gather + combine + leaky + tf32-round -> hs ----
        {
            int ebase = tile * EPB + warp * 16;
            int e  = ebase + (lane & 15);
            int ec = e < E ? e : (E - 1);
            long long pos = (lane < 16) ? (long long)ec : (long long)E + ec;
            long long v = load_idx(ell, pos, is64);

#pragma unroll
            for (int t = 0; t < 16; t++) {
                long long i = __shfl_sync(0xffffffffu, v, t);
                long long j = __shfl_sync(0xffffffffu, v, 16 + t);
                const float4 a = *(const float4*)&g_hd[i * 128 + lane * 4];
                const float4 b = *(const float4*)&g_he[j * 128 + lane * 4];
                uint4 s;
                s.x = f2tf32(lrelu(a.x + b.x));
                s.y = f2tf32(lrelu(a.y + b.y));
                s.z = f2tf32(lrelu(a.z + b.z));
                s.w = f2tf32(lrelu(a.w + b.w));
                *(uint4*)&hw[t * HS_STRIDE + lane * 4] = s;
            }
        }
        __syncwarp();

        // ---- phase 2: D[16e x 32m] via 16 ksteps x 4 n-blocks of mma ----
        float acc[4][4];
#pragma unroll
        for (int nb = 0; nb < 4; nb++)
#pragma unroll
            for (int q = 0; q < 4; q++) acc[nb][q] = 0.0f;

#pragma unroll
        for (int ks = 0; ks < 16; ks++) {
            const int k0 = ks * 8;
            uint32_t a0 = r0[k0 + c];
            uint32_t a1 = r1[k0 + c];
            uint32_t a2 = r0[k0 + c + 4];
            uint32_t a3 = r1[k0 + c + 4];
#pragma unroll
            for (int nb = 0; nb < 4; nb++) {
                uint2 bb = bfl[(ks * 4 + nb) * 32];
                mma8(acc[nb], a0, a1, a2, a3, bb.x, bb.y);
            }
        }
        __syncwarp();   // hs consumed; safe to rewrite next tile

        // ---- phase 3: bias+leaky, layer 3 partials, shfl-reduce, layer 4 ----
        // lane holds D rows (warp*16+g) and (+8), cols m = nb*8 + 2c + q
        {
            ull p0[8], p1[8];
#pragma unroll
            for (int p = 0; p < 8; p++) { p0[p] = 0ull; p1[p] = 0ull; }

#pragma unroll
            for (int nb = 0; nb < 4; nb++) {
#pragma unroll
                for (int q = 0; q < 2; q++) {
                    int m = nb * 8 + 2 * c + q;
                    float o0 = lrelu(acc[nb][q]     + b2s[m]);
                    float o1 = lrelu(acc[nb][2 + q] + b2s[m]);
                    ull x0 = pk2(o0, o0);
                    ull x1 = pk2(o1, o1);
                    const ulonglong2 wA = *(const ulonglong2*)&w3s[m * 16 + 0];
                    const ulonglong2 wB = *(const ulonglong2*)&w3s[m * 16 + 4];
                    const ulonglong2 wC = *(const ulonglong2*)&w3s[m * 16 + 8];
                    const ulonglong2 wD = *(const ulonglong2*)&w3s[m * 16 + 12];
                    p0[0] = fma2(x0, wA.x, p0[0]);  p1[0] = fma2(x1, wA.x, p1[0]);
                    p0[1] = fma2(x0, wA.y, p0[1]);  p1[1] = fma2(x1, wA.y, p1[1]);
                    p0[2] = fma2(x0, wB.x, p0[2]);  p1[2] = fma2(x1, wB.x, p1[2]);
                    p0[3] = fma2(x0, wB.y, p0[3]);  p1[3] = fma2(x1, wB.y, p1[3]);
                    p0[4] = fma2(x0, wC.x, p0[4]);  p1[4] = fma2(x1, wC.x, p1[4]);
                    p0[5] = fma2(x0, wC.y, p0[5]);  p1[5] = fma2(x1, wC.y, p1[5]);
                    p0[6] = fma2(x0, wD.x, p0[6]);  p1[6] = fma2(x1, wD.x, p1[6]);
                    p0[7] = fma2(x0, wD.y, p0[7]);  p1[7] = fma2(x1, wD.y, p1[7]);
                }
            }

            // reduce across the 4 lanes (c = 0..3) sharing each edge row
#pragma unroll
            for (int d = 1; d <= 2; d <<= 1) {
#pragma unroll
                for (int p = 0; p < 8; p++) {
                    p0[p] = add2(p0[p], __shfl_xor_sync(0xffffffffu, p0[p], d));
                    p1[p] = add2(p1[p], __shfl_xor_sync(0xffffffffu, p1[p], d));
                }
            }

            if (c == 0) {
                float y0 = b4v, y1 = b4v;
#pragma unroll
                for (int p = 0; p < 8; p++) {
                    float a, b;
                    up2(p0[p], a, b);
                    y0 = fmaf(lrelu(a + b3s[2 * p]),     w4s[2 * p],     y0);
                    y0 = fmaf(lrelu(b + b3s[2 * p + 1]), w4s[2 * p + 1], y0);
                    up2(p1[p], a, b);
                    y1 = fmaf(lrelu(a + b3s[2 * p]),     w4s[2 * p],     y1);
                    y1 = fmaf(lrelu(b + b3s[2 * p + 1]), w4s[2 * p + 1], y1);
                }
                int e0 = tile * EPB + warp * 16 + g;
                if (e0 < E)     out[e0]     = y0;
                if (e0 + 8 < E) out[e0 + 8] = y1;
            }
        }
    }
}

// ---------------------------------------------------------------------------
extern "C" void kernel_launch(void* const* d_in, const int* in_sizes, int n_in,
                              void* d_out, int out_size) {
    const float* xd  = (const float*)d_in[0];
    const float* xs  = (const float*)d_in[1];
    const void*  ell = d_in[2];
    const float* W1  = (const float*)d_in[3];
    const float* b1  = (const float*)d_in[4];
    const float* W2  = (const float*)d_in[5];
    const float* b2  = (const float*)d_in[6];
    const float* W3  = (const float*)d_in[7];
    const float* b3  = (const float*)d_in[8];
    const float* W4  = (const float*)d_in[9];
    const float* b4  = (const float*)d_in[10];
    float* out = (float*)d_out;

    int n_drug = in_sizes[0] / 100;
    int n_dis  = in_sizes[1] / 100;
    int E      = in_sizes[2] / 2;

    int nb_drug = (n_drug + NB - 1) / NB;
    int nb_dis  = (n_dis  + NB - 1) / NB;
    int node_smem = (12800 + 100 * NB) * 4;
    cudaFuncSetAttribute(node_precompute,
                         cudaFuncAttributeMaxDynamicSharedMemorySize, node_smem);
    node_precompute<<<nb_drug + nb_dis, 256, node_smem>>>(
        xd, xs, W1, b1, (const long long*)ell, n_drug, n_dis, nb_drug);

    cudaFuncSetAttribute(edge_mlp_kernel,
                         cudaFuncAttributeMaxDynamicSharedMemorySize, SMEM_BYTES);
    int n_tiles = (E + EPB - 1) / EPB;
    int grid = 2 * 148;
    if (grid > n_tiles) grid = n_tiles;
    edge_mlp_kernel<<<grid, NTHR, SMEM_BYTES>>>(ell, W2, b2, W3, b3, W4, b4,
                                                out, E, n_tiles);
}